// round 9
// baseline (speedup 1.0000x reference)
#include <cuda_runtime.h>
#include <cuda_bf16.h>
#include <cstdint>
#include <math.h>

// ---------------------------------------------------------------------------
// Problem constants
// ---------------------------------------------------------------------------
#define NHALF 8192
#define NROWS 16384
#define DDIM 256
#define TILE 128
#define NBLK (NROWS / TILE)        // 128 row/col blocks
#define NPAIRS 8256                // NBLK*(NBLK+1)/2 upper-tri tile pairs
#define GRID_G 148                 // persistent CTAs (one wave on 148 SMs)
#define INV_TAU_LOG2E 2.8853900817779268f   // (1/tau) * log2(e), tau = 0.5
#define E2 7.38905609893065f                // exp(2.0) = refl diagonal
#define LN2F 0.6931471805599453f

#define TILE_BYTES (TILE * DDIM * 2)        // 65536 bytes (128 rows x 256 bf16)

// Scratch (static device arrays; no allocations allowed)
__device__ __align__(256) __nv_bfloat16 g_X[NROWS * DDIM];   // 8 MB normalized bf16
__device__ float g_rowsum[NROWS];
__device__ float g_posdot[NHALF];

// ---------------------------------------------------------------------------
// PTX helpers (plain sm_103-legal ISA only: ldmatrix / mma.sync / cp.async)
// ---------------------------------------------------------------------------
__device__ __forceinline__ float ex2_approx(float x) {
    float r;
    asm("ex2.approx.ftz.f32 %0, %1;" : "=f"(r) : "f"(x));
    return r;
}

__device__ __forceinline__ float lg2_approx(float x) {
    float r;
    asm("lg2.approx.ftz.f32 %0, %1;" : "=f"(r) : "f"(x));
    return r;
}

__device__ __forceinline__ uint32_t smem_u32(const void* p) {
    uint32_t a;
    asm("{ .reg .u64 t; cvta.to.shared.u64 t, %1; cvt.u32.u64 %0, t; }" : "=r"(a) : "l"(p));
    return a;
}

#define CP_COMMIT() asm volatile("cp.async.commit_group;" ::: "memory")
#define CP_WAIT1()  asm volatile("cp.async.wait_group 1;" ::: "memory")
#define CP_WAIT0()  asm volatile("cp.async.wait_group 0;" ::: "memory")

// Blocked-atom SW128 address for element (row, colb16) inside a 128x256 bf16 tile.
__device__ __forceinline__ uint32_t tile_addr(uint32_t base, int row, int colb16) {
    uint32_t byte = (uint32_t)(((row >> 3) + (colb16 >> 6) * 16) * 1024 +
                               (row & 7) * 128 + (colb16 & 63) * 2);
    byte ^= (byte >> 3) & 0x70;            // SW128 swizzle
    return base + byte;
}

// Async-copy one 128x256 bf16 tile (row-major global) into blocked-atom SW128 SMEM.
__device__ __forceinline__ void cp_tile_async(uint32_t dst_base, const char* __restrict__ src,
                                              int tid) {
#pragma unroll
    for (int k = 0; k < 16; ++k) {
        int idx = tid + k * 256;               // row*32 + q
        int row = idx >> 5;
        int q = idx & 31;
        uint32_t byte = (uint32_t)(((row >> 3) + (q >> 3) * 16) * 1024 +
                                   (row & 7) * 128 + (q & 7) * 16);
        byte ^= (byte >> 3) & 0x70;
        asm volatile("cp.async.cg.shared.global [%0], [%1], 16;"
                     :: "r"(dst_base + byte), "l"(src + (size_t)idx * 16) : "memory");
    }
}

__device__ __forceinline__ void ldsm_x4(uint32_t addr, uint32_t& r0, uint32_t& r1,
                                        uint32_t& r2, uint32_t& r3) {
    asm volatile("ldmatrix.sync.aligned.m8n8.x4.shared.b16 {%0,%1,%2,%3}, [%4];"
                 : "=r"(r0), "=r"(r1), "=r"(r2), "=r"(r3) : "r"(addr));
}

__device__ __forceinline__ void mma16816(float& c0, float& c1, float& c2, float& c3,
                                         uint32_t a0, uint32_t a1, uint32_t a2, uint32_t a3,
                                         uint32_t b0, uint32_t b1) {
    asm volatile("mma.sync.aligned.m16n8k16.row.col.f32.bf16.bf16.f32 "
                 "{%0,%1,%2,%3}, {%4,%5,%6,%7}, {%8,%9}, {%0,%1,%2,%3};"
                 : "+f"(c0), "+f"(c1), "+f"(c2), "+f"(c3)
                 : "r"(a0), "r"(a1), "r"(a2), "r"(a3), "r"(b0), "r"(b1));
}

// ---------------------------------------------------------------------------
// SMEM layout for GEMM kernel
// ---------------------------------------------------------------------------
#define SM_A 0
#define SM_B0 65536
#define SM_B1 131072
#define SM_TOTAL 196608            // 192 KB -> 1 CTA/SM

// ---------------------------------------------------------------------------
// Tile body: MMA tile into `cur`; concurrently (interleaved in-issue-order so
// MUFU overlaps the tensor pipe) exp-drain `prv` (previous tile) into
// rowacc/colacc. 4 exps per K-step: ks -> (mf = ks>>2, nf = ks&3).
// ---------------------------------------------------------------------------
struct LaneGeom {
    uint32_t abase;
    int a_row, a_col;   // per-lane ldmatrix offsets for A
    int b_row, b_col;   // per-lane ldmatrix offsets for B
    int wm, wn;
};

__device__ __forceinline__ void tile_body(float (&cur)[4][4][4], float (&prv)[4][4][4],
                                          bool do_prev, uint32_t bbase, const LaneGeom& G,
                                          float (&rowacc)[8], float (&colacc)[8]) {
#pragma unroll
    for (int mf = 0; mf < 4; ++mf)
#pragma unroll
        for (int nf = 0; nf < 4; ++nf)
#pragma unroll
            for (int r = 0; r < 4; ++r) cur[mf][nf][r] = 0.0f;
    if (do_prev) {
#pragma unroll
        for (int r = 0; r < 8; ++r) colacc[r] = 0.0f;
    }

#pragma unroll
    for (int ks = 0; ks < 16; ++ks) {
        const int kcol = ks * 16;
        uint32_t a[4][4];
#pragma unroll
        for (int mf = 0; mf < 4; ++mf)
            ldsm_x4(tile_addr(G.abase, G.wm * 64 + mf * 16 + G.a_row, kcol + G.a_col),
                    a[mf][0], a[mf][1], a[mf][2], a[mf][3]);
        uint32_t b[4][2];
#pragma unroll
        for (int p = 0; p < 2; ++p) {
            uint32_t r0, r1, r2, r3;
            ldsm_x4(tile_addr(bbase, G.wn * 32 + p * 16 + G.b_row, kcol + G.b_col),
                    r0, r1, r2, r3);
            b[p * 2 + 0][0] = r0; b[p * 2 + 0][1] = r1;
            b[p * 2 + 1][0] = r2; b[p * 2 + 1][1] = r3;
        }
#pragma unroll
        for (int mf = 0; mf < 4; ++mf)
#pragma unroll
            for (int nf = 0; nf < 4; ++nf)
                mma16816(cur[mf][nf][0], cur[mf][nf][1], cur[mf][nf][2], cur[mf][nf][3],
                         a[mf][0], a[mf][1], a[mf][2], a[mf][3],
                         b[nf][0], b[nf][1]);

        // interleaved exp-drain of previous tile (MUFU; hides under HMMA)
        if (do_prev) {
            const int mf = ks >> 2, nf = ks & 3;
            float e0 = ex2_approx(prv[mf][nf][0] * INV_TAU_LOG2E);
            float e1 = ex2_approx(prv[mf][nf][1] * INV_TAU_LOG2E);
            float e2 = ex2_approx(prv[mf][nf][2] * INV_TAU_LOG2E);
            float e3 = ex2_approx(prv[mf][nf][3] * INV_TAU_LOG2E);
            rowacc[mf * 2 + 0] += e0 + e1;
            rowacc[mf * 2 + 1] += e2 + e3;
            colacc[nf * 2 + 0] += e0 + e2;
            colacc[nf * 2 + 1] += e1 + e3;
        }
    }
}

// Drain a tile's accumulators without a concurrent MMA (used for the run's last tile).
__device__ __forceinline__ void tile_drain(float (&prv)[4][4][4],
                                           float (&rowacc)[8], float (&colacc)[8]) {
#pragma unroll
    for (int r = 0; r < 8; ++r) colacc[r] = 0.0f;
#pragma unroll
    for (int mf = 0; mf < 4; ++mf)
#pragma unroll
        for (int nf = 0; nf < 4; ++nf) {
            float e0 = ex2_approx(prv[mf][nf][0] * INV_TAU_LOG2E);
            float e1 = ex2_approx(prv[mf][nf][1] * INV_TAU_LOG2E);
            float e2 = ex2_approx(prv[mf][nf][2] * INV_TAU_LOG2E);
            float e3 = ex2_approx(prv[mf][nf][3] * INV_TAU_LOG2E);
            rowacc[mf * 2 + 0] += e0 + e1;
            rowacc[mf * 2 + 1] += e2 + e3;
            colacc[nf * 2 + 0] += e0 + e2;
            colacc[nf * 2 + 1] += e1 + e3;
        }
}

// Col-sum flush for tile column-block j (validated mapping from R8).
__device__ __forceinline__ void flush_col(float (&colacc)[8], int j, int wn, int lane) {
#pragma unroll
    for (int r = 0; r < 8; ++r) {
        float v = colacc[r];
        v += __shfl_xor_sync(0xffffffffu, v, 4);
        v += __shfl_xor_sync(0xffffffffu, v, 8);
        v += __shfl_xor_sync(0xffffffffu, v, 16);
        if (lane < 4)
            atomicAdd(&g_rowsum[(size_t)j * TILE + wn * 32 + (r >> 1) * 8 +
                                lane * 2 + (r & 1)], v);
    }
}

// ---------------------------------------------------------------------------
// Kernel 1: normalize rows (warp-per-row), write bf16 X = [an; bn],
//           compute pos dot (fp32), zero g_rowsum for gemm atomics.
// ---------------------------------------------------------------------------
__global__ void __launch_bounds__(256) normalize_kernel(const float* __restrict__ z1,
                                                         const float* __restrict__ z2) {
    const int tid = threadIdx.x;
    const int wid = tid >> 5, lane = tid & 31;
    const int i = blockIdx.x * 8 + wid;        // input row [0, 8192)

    if (tid < 16) g_rowsum[(size_t)blockIdx.x * 16 + tid] = 0.0f;

    const float4* za = reinterpret_cast<const float4*>(z1 + (size_t)i * DDIM);
    const float4* zb = reinterpret_cast<const float4*>(z2 + (size_t)i * DDIM);
    float4 a0 = za[lane], a1 = za[lane + 32];
    float4 b0 = zb[lane], b1 = zb[lane + 32];

    float va = a0.x*a0.x + a0.y*a0.y + a0.z*a0.z + a0.w*a0.w
             + a1.x*a1.x + a1.y*a1.y + a1.z*a1.z + a1.w*a1.w;
    float vb = b0.x*b0.x + b0.y*b0.y + b0.z*b0.z + b0.w*b0.w
             + b1.x*b1.x + b1.y*b1.y + b1.z*b1.z + b1.w*b1.w;
    float vd = a0.x*b0.x + a0.y*b0.y + a0.z*b0.z + a0.w*b0.w
             + a1.x*b1.x + a1.y*b1.y + a1.z*b1.z + a1.w*b1.w;
#pragma unroll
    for (int o = 16; o; o >>= 1) {
        va += __shfl_xor_sync(0xffffffffu, va, o);
        vb += __shfl_xor_sync(0xffffffffu, vb, o);
        vd += __shfl_xor_sync(0xffffffffu, vd, o);
    }
    const float ia = rsqrtf(fmaxf(va, 1e-24f));   // norms ~16 >> eps
    const float ib = rsqrtf(fmaxf(vb, 1e-24f));
    if (lane == 0) g_posdot[i] = vd * ia * ib;

    uint2* oa = reinterpret_cast<uint2*>(g_X + (size_t)i * DDIM);
    uint2* ob = reinterpret_cast<uint2*>(g_X + (size_t)(NHALF + i) * DDIM);
    uint2 pa0, pa1, pb0, pb1;
    __nv_bfloat162 h;
    h = __floats2bfloat162_rn(a0.x * ia, a0.y * ia); pa0.x = *reinterpret_cast<uint32_t*>(&h);
    h = __floats2bfloat162_rn(a0.z * ia, a0.w * ia); pa0.y = *reinterpret_cast<uint32_t*>(&h);
    h = __floats2bfloat162_rn(a1.x * ia, a1.y * ia); pa1.x = *reinterpret_cast<uint32_t*>(&h);
    h = __floats2bfloat162_rn(a1.z * ia, a1.w * ia); pa1.y = *reinterpret_cast<uint32_t*>(&h);
    h = __floats2bfloat162_rn(b0.x * ib, b0.y * ib); pb0.x = *reinterpret_cast<uint32_t*>(&h);
    h = __floats2bfloat162_rn(b0.z * ib, b0.w * ib); pb0.y = *reinterpret_cast<uint32_t*>(&h);
    h = __floats2bfloat162_rn(b1.x * ib, b1.y * ib); pb1.x = *reinterpret_cast<uint32_t*>(&h);
    h = __floats2bfloat162_rn(b1.z * ib, b1.w * ib); pb1.y = *reinterpret_cast<uint32_t*>(&h);
    oa[lane] = pa0; oa[lane + 32] = pa1;
    ob[lane] = pb0; ob[lane + 32] = pb1;
}

// ---------------------------------------------------------------------------
// Kernel 2: symmetric exp-rowsum GEMM, software-pipelined epilogue.
// Upper-triangle tiles only; tile (i,j): row-sums -> block i, col-sums -> block j.
// Previous tile's exp-drain is interleaved into the current tile's MMA loop.
// ---------------------------------------------------------------------------
__global__ void __launch_bounds__(256, 1) gemm_rowsum_kernel() {
    extern __shared__ char smem[];
    const uint32_t sbase = smem_u32(smem);
    const int tid = threadIdx.x;
    const int wid = tid >> 5, lane = tid & 31;

    LaneGeom G;
    G.abase = sbase + SM_A;
    G.wm = wid >> 2;
    G.wn = wid & 3;
    G.a_row = lane & 15;
    G.a_col = (lane >> 4) * 8;
    G.b_row = (lane & 7) + ((lane >> 4) & 1) * 8;
    G.b_col = ((lane >> 3) & 1) * 8;

    const char* Xb = reinterpret_cast<const char*>(g_X);

    int g        = (int)(((long long)blockIdx.x * NPAIRS) / GRID_G);
    const int g1 = (int)(((long long)(blockIdx.x + 1) * NPAIRS) / GRID_G);

    float c0[4][4][4], c1[4][4][4];
    float rowacc[8], colacc[8];

    while (g < g1) {
        // decode run: strip s, local index t0; boundary between the two i-legs
        const int s  = g / 129;
        const int t0 = g - s * 129;
        const int bnd = 128 - s;
        int i, j0, rend;
        if (t0 < bnd) { i = s;       j0 = s + t0;                 rend = s * 129 + bnd; }
        else          { i = 127 - s; j0 = (127 - s) + (t0 - bnd); rend = (s + 1) * 129; }
        int cnt = min(rend, g1) - g;

        // ---- stream run: fixed i, j = j0..j0+cnt-1 ----
        cp_tile_async(sbase + SM_A, Xb + (size_t)i * TILE_BYTES, tid);
        CP_COMMIT();
        cp_tile_async(sbase + SM_B0, Xb + (size_t)j0 * TILE_BYTES, tid);
        CP_COMMIT();
        if (cnt > 1) cp_tile_async(sbase + SM_B1, Xb + (size_t)(j0 + 1) * TILE_BYTES, tid);
        CP_COMMIT();   // may be an empty group (cnt==1)

#pragma unroll
        for (int r = 0; r < 8; ++r) rowacc[r] = 0.0f;

        for (int t = 0; t < cnt; ++t) {
            if (t == cnt - 1) CP_WAIT0(); else CP_WAIT1();
            __syncthreads();

            const uint32_t bbase = sbase + ((t & 1) ? SM_B1 : SM_B0);
            const bool dp = (t > 0);
            const int jprev = j0 + t - 1;

            if ((t & 1) == 0) tile_body(c0, c1, dp, bbase, G, rowacc, colacc);
            else              tile_body(c1, c0, dp, bbase, G, rowacc, colacc);

            if (dp && jprev != i) flush_col(colacc, jprev, G.wn, lane);

            __syncthreads();       // everyone done reading buf[t&1]
            if (t + 2 < cnt) {
                cp_tile_async(bbase, Xb + (size_t)(j0 + t + 2) * TILE_BYTES, tid);
                CP_COMMIT();
            }
        }

        // drain the run's last tile
        const int jlast = j0 + cnt - 1;
        if ((cnt - 1) & 1) tile_drain(c1, rowacc, colacc);
        else               tile_drain(c0, rowacc, colacc);
        if (jlast != i) flush_col(colacc, jlast, G.wn, lane);

        // row sums for block i
#pragma unroll
        for (int r = 0; r < 8; ++r) {
            float v = rowacc[r];
            v += __shfl_xor_sync(0xffffffffu, v, 1);
            v += __shfl_xor_sync(0xffffffffu, v, 2);
            if ((lane & 3) == 0)
                atomicAdd(&g_rowsum[(size_t)i * TILE + G.wm * 64 + (r >> 1) * 16 +
                                    (lane >> 2) + (r & 1) * 8], v);
        }

        g += cnt;
    }
}

// ---------------------------------------------------------------------------
// Kernel 3: final scalar reduction
// loss = scale * sum_i [ log(rs[i]-e^2) + log(rs[N+i]-e^2) - 4*posdot[i] ]
// ---------------------------------------------------------------------------
__global__ void __launch_bounds__(256) finalize_kernel(const int* __restrict__ meanp,
                                                        float* __restrict__ out) {
    const int t = threadIdx.x;
    const int w = t >> 5, l = t & 31;
    __shared__ float sh[8];
    float s = 0.0f;
    for (int i = t; i < NHALF; i += 256) {
        s += (lg2_approx(g_rowsum[i] - E2) + lg2_approx(g_rowsum[NHALF + i] - E2)) * LN2F
             - 4.0f * g_posdot[i];
    }
#pragma unroll
    for (int o = 16; o; o >>= 1) s += __shfl_xor_sync(0xffffffffu, s, o);
    if (l == 0) sh[w] = s;
    __syncthreads();
    if (t == 0) {
        float tot = 0.f;
        for (int k = 0; k < 8; ++k) tot += sh[k];
        float scale = (*meanp != 0) ? (0.5f / (float)NHALF) : 0.5f;
        out[0] = tot * scale;
    }
}

// ---------------------------------------------------------------------------
extern "C" void kernel_launch(void* const* d_in, const int* in_sizes, int n_in,
                              void* d_out, int out_size) {
    (void)in_sizes; (void)n_in; (void)out_size;
    const float* z1 = (const float*)d_in[0];
    const float* z2 = (const float*)d_in[1];
    const int* meanp = (const int*)d_in[2];
    float* out = (float*)d_out;

    cudaFuncSetAttribute(gemm_rowsum_kernel,
                         cudaFuncAttributeMaxDynamicSharedMemorySize, SM_TOTAL);

    normalize_kernel<<<NHALF / 8, 256>>>(z1, z2);
    gemm_rowsum_kernel<<<GRID_G, 256, SM_TOTAL>>>();
    finalize_kernel<<<1, 256>>>(meanp, out);
}